// round 8
// baseline (speedup 1.0000x reference)
#include <cuda_runtime.h>
#include <cuda_bf16.h>
#include <math.h>
#include <stdint.h>

#define LYRS   2
#define HDIM   512
#define NHEAD  32
#define BATCH  8
#define SEQ    4096
#define MROWS  (BATCH*SEQ)
#define BLH    (MROWS*HDIM)

// GEMM tiling: CTA 128x128, 8 warps of 64x32, K-chunks of 32, double buffer,
// hi|lo packed per 128B smem row -> stage 32KB -> 2 CTAs/SM.
#define BM 128
#define BN 128
#define BK 32
#define STAGE_B 32768                /* A 16K (hi|lo packed) + W 16K */
#define SM_ST   1024
#define GEMM_SMEM (SM_ST + 2*STAGE_B)   /* 66560 */

// ---------------- scratch ----------------------------------------------------
__device__ float Fz[BLH], Fo1[BLH], Ftmp[BLH], FoutB[BLH];
__device__ __nv_bfloat16 P0h[BLH], P0l[BLH], P1h[BLH], P1l[BLH];
__device__ __nv_bfloat16 WTh[10*HDIM*HDIM], WTl[10*HDIM*HDIM];
__device__ float g_lam_re[LYRS*HDIM*NHEAD], g_lam_im[LYRS*HDIM*NHEAD];
__device__ float g_co_re [LYRS*HDIM*NHEAD], g_co_im [LYRS*HDIM*NHEAD];

// ---------------- PTX helpers --------------------------------------------------
__device__ __forceinline__ uint32_t smem_u32(const void* p) {
    uint32_t a;
    asm("{ .reg .u64 t; cvta.to.shared.u64 t, %1; cvt.u32.u64 %0, t; }"
        : "=r"(a) : "l"(p));
    return a;
}
#define CP16(dst, src) \
    asm volatile("cp.async.cg.shared.global [%0], [%1], 16;" \
        :: "r"(dst), "l"(src) : "memory")
#define CP_COMMIT() asm volatile("cp.async.commit_group;" ::: "memory")
#define CP_WAIT(n)  asm volatile("cp.async.wait_group %0;" :: "n"(n) : "memory")

#define LDSM_X4(r0,r1,r2,r3, addr) \
    asm volatile("ldmatrix.sync.aligned.m8n8.x4.shared.b16 {%0,%1,%2,%3}, [%4];" \
        : "=r"(r0),"=r"(r1),"=r"(r2),"=r"(r3) : "r"(addr))

#define MMA16816(d, a0,a1,a2,a3, b0,b1) \
    asm volatile("mma.sync.aligned.m16n8k16.row.col.f32.bf16.bf16.f32 " \
        "{%0,%1,%2,%3}, {%4,%5,%6,%7}, {%8,%9}, {%0,%1,%2,%3};" \
        : "+f"((d)[0]),"+f"((d)[1]),"+f"((d)[2]),"+f"((d)[3]) \
        : "r"(a0),"r"(a1),"r"(a2),"r"(a3), "r"(b0),"r"(b1))

__device__ __forceinline__ uint32_t swz(uint32_t off) { return off ^ ((off >> 3) & 0x70); }
__device__ __forceinline__ float gelu_f(float x) {
    return 0.5f * x * (1.0f + erff(x * 0.70710678118654752440f));
}
__device__ __forceinline__ void split_bf(float v, __nv_bfloat16& h, __nv_bfloat16& l) {
    h = __float2bfloat16(v);
    l = __float2bfloat16(v - __bfloat162float(h));
}

// ---------------- SSM coefficient precompute ----------------------------------
__global__ void prec_k(const float* __restrict__ log_dt,
                       const float* __restrict__ A_re, const float* __restrict__ A_im,
                       const float* __restrict__ B_re, const float* __restrict__ B_im,
                       const float* __restrict__ C_re, const float* __restrict__ C_im)
{
    int idx = blockIdx.x * blockDim.x + threadIdx.x;
    if (idx >= LYRS*HDIM*NHEAD) return;
    int lh = idx / NHEAD;
    float dt = expf(log_dt[lh]);
    float ar = A_re[idx], ai = A_im[idx];
    float e = expf(dt*ar);
    float sn, cs; sincosf(dt*ai, &sn, &cs);
    float lr = e*cs, li = e*sn;
    float nr = lr - 1.0f, ni = li;
    float inv = 1.0f/(ar*ar + ai*ai);
    float dr = (nr*ar + ni*ai)*inv;
    float di = (ni*ar - nr*ai)*inv;
    float br = B_re[idx], bi = B_im[idx];
    float dbr = br*dr - bi*di;
    float dbi = br*di + bi*dr;
    float cr = C_re[idx], ci = C_im[idx];
    g_co_re[idx] = 2.0f*(cr*dbr - ci*dbi);
    g_co_im[idx] = 2.0f*(cr*dbi + ci*dbr);
    g_lam_re[idx] = lr;
    g_lam_im[idx] = li;
}

// ---------------- weight transpose + hi/lo split --------------------------------
__global__ void wconv_k(const float* __restrict__ Wk, const float* __restrict__ W1,
                        const float* __restrict__ Wproj, const float* __restrict__ W2,
                        const float* __restrict__ Wout)
{
    int widx = blockIdx.z;
    int l = widx / 5, t = widx % 5;
    const float* src = (t==0 ? Wk : t==1 ? W1 : t==2 ? Wproj : t==3 ? W2 : Wout)
                       + (size_t)l * HDIM * HDIM;
    __shared__ float tile[32][33];
    int tx = threadIdx.x, ty = threadIdx.y;
    int n0 = blockIdx.x*32, k0 = blockIdx.y*32;
    #pragma unroll
    for (int i = 0; i < 4; ++i)
        tile[ty + 8*i][tx] = src[(size_t)(k0 + ty + 8*i)*HDIM + n0 + tx];
    __syncthreads();
    #pragma unroll
    for (int i = 0; i < 4; ++i) {
        float v = tile[tx][ty + 8*i];
        size_t o = (size_t)widx*HDIM*HDIM + (size_t)(n0 + ty + 8*i)*HDIM + k0 + tx;
        __nv_bfloat16 h, lo; split_bf(v, h, lo);
        WTh[o] = h; WTl[o] = lo;
    }
}

// ---------------- activation transpose [B,L,H] -> [B,H,L] ----------------------
__global__ void __launch_bounds__(256)
tr_k(const float* __restrict__ src, float* __restrict__ dst)
{
    __shared__ float tile[32][33];
    const int tx = threadIdx.x, ty = threadIdx.y;
    const int t0 = blockIdx.x * 32;
    const int h0 = blockIdx.y * 32;
    const int b  = blockIdx.z;
    const float* sp = src + ((size_t)b*SEQ + t0)*HDIM + h0;
    #pragma unroll
    for (int i = 0; i < 4; ++i)
        tile[ty + 8*i][tx] = sp[(size_t)(ty + 8*i)*HDIM + tx];
    __syncthreads();
    float* dp = dst + ((size_t)b*HDIM + h0)*SEQ + t0;
    #pragma unroll
    for (int i = 0; i < 4; ++i)
        dp[(size_t)(ty + 8*i)*SEQ + tx] = tile[tx][ty + 8*i];
}

// ---------------- LayerNorm (MODE 0: fp32 out ; MODE 1: bf16 hi/lo out) --------
template<int MODE>
__global__ void __launch_bounds__(128)
ln_k(const float* __restrict__ src, const float* __restrict__ g,
     const float* __restrict__ b, float* __restrict__ dstf,
     __nv_bfloat16* __restrict__ dsth, __nv_bfloat16* __restrict__ dstl)
{
    const int m = blockIdx.x, tid = threadIdx.x;
    const float4 v = *(const float4*)(src + (size_t)m*HDIM + tid*4);
    float s = v.x + v.y + v.z + v.w;
    float q = v.x*v.x + v.y*v.y + v.z*v.z + v.w*v.w;
    #pragma unroll
    for (int o = 16; o; o >>= 1) {
        s += __shfl_xor_sync(0xffffffffu, s, o);
        q += __shfl_xor_sync(0xffffffffu, q, o);
    }
    __shared__ float ss[4], qq[4], mu_s, rs_s;
    int w = tid >> 5;
    if ((tid & 31) == 0) { ss[w] = s; qq[w] = q; }
    __syncthreads();
    if (tid == 0) {
        float S = ss[0]+ss[1]+ss[2]+ss[3];
        float Q = qq[0]+qq[1]+qq[2]+qq[3];
        float mu = S*(1.0f/HDIM);
        mu_s = mu; rs_s = rsqrtf(Q*(1.0f/HDIM) - mu*mu + 1e-5f);
    }
    __syncthreads();
    const float mu = mu_s, rs = rs_s;
    const float4 gv = *(const float4*)(g + tid*4);
    const float4 bv = *(const float4*)(b + tid*4);
    float4 o;
    o.x = (v.x - mu)*rs*gv.x + bv.x;
    o.y = (v.y - mu)*rs*gv.y + bv.y;
    o.z = (v.z - mu)*rs*gv.z + bv.z;
    o.w = (v.w - mu)*rs*gv.w + bv.w;
    size_t off = (size_t)m*HDIM + tid*4;
    if (MODE == 0) {
        *(float4*)(dstf + off) = o;
    } else {
        __nv_bfloat16 h0,h1,h2,h3,l0,l1,l2,l3;
        split_bf(o.x,h0,l0); split_bf(o.y,h1,l1);
        split_bf(o.z,h2,l2); split_bf(o.w,h3,l3);
        __nv_bfloat162 a0, a1, c0, c1;
        a0.x=h0; a0.y=h1; a1.x=h2; a1.y=h3;
        c0.x=l0; c0.y=l1; c1.x=l2; c1.y=l3;
        *(uint2*)(dsth + off) = make_uint2(*(uint32_t*)&a0, *(uint32_t*)&a1);
        *(uint2*)(dstl + off) = make_uint2(*(uint32_t*)&c0, *(uint32_t*)&c1);
    }
}

// ---------------- S4 scan + D-skip + GELU (R6 version) --------------------------
__global__ void __launch_bounds__(256)
scan_k(const float* __restrict__ zt, __nv_bfloat16* __restrict__ yh,
       __nv_bfloat16* __restrict__ yl, const float* __restrict__ Dvec, int l)
{
    __shared__ float st_s[8][32*36];
    __shared__ float zst[8][32];
    __shared__ float yt[2][32][9];
    const int tid  = threadIdx.x;
    const int wid  = tid >> 5;
    const int lane = tid & 31;
    const int b    = blockIdx.x >> 6;
    const int hg   = blockIdx.x & 63;
    const int h    = hg*8 + wid;
    const int base = l*HDIM*NHEAD + h*NHEAD + lane;
    const float lr = g_lam_re[base], li = g_lam_im[base];
    const float cr = g_co_re[base],  ci = g_co_im[base];
    const float nci = -ci;
    const float dsk = Dvec[h];
    const float* zp = zt + ((size_t)b*HDIM + h)*SEQ;
    float* st = st_s[wid];
    float* zs = zst[wid];
    const int ot = tid >> 3, oh = tid & 7;
    float sr = 0.0f, si = 0.0f;

    for (int t0 = 0; t0 < SEQ; t0 += 32) {
        float zv = zp[t0 + lane];
        zs[lane] = zv;
        __syncwarp();
        #pragma unroll
        for (int tt = 0; tt < 32; ++tt) {
            float zv_t = zs[tt];
            float tmp  = fmaf(-li, si, zv_t);
            float nsi  = fmaf(li, sr, lr*si);
            sr = fmaf(lr, sr, tmp);
            si = nsi;
            st[tt*36 + lane] = fmaf(cr, sr, nci*si);
        }
        __syncwarp();
        float a0 = 0.f, a1 = 0.f, a2 = 0.f, a3 = 0.f;
        const float4* rp = (const float4*)&st[lane*36];
        #pragma unroll
        for (int i = 0; i < 8; ++i) {
            float4 v4 = rp[i];
            a0 += v4.x; a1 += v4.y; a2 += v4.z; a3 += v4.w;
        }
        const int buf = (t0 >> 5) & 1;
        yt[buf][lane][wid] = gelu_f((a0 + a1) + (a2 + a3) + dsk * zv);
        __syncthreads();
        float v = yt[buf][ot][oh];
        __nv_bfloat16 hh, ll; split_bf(v, hh, ll);
        size_t off = ((size_t)(b*SEQ + t0 + ot))*HDIM + hg*8 + oh;
        yh[off] = hh; yl[off] = ll;
    }
}

// ---------------- bf16x3 mma.sync GEMM: 256 thr, 128x128, BK=32, occ 2 ----------
// smem row (128B) packs [hi(64B) | lo(64B)]. All cp.async dests use swz(full
// offset) — the swizzle is NOT linear in +16 (R7 crash root cause).
template<int EPI, bool WF32, bool WHL>
__global__ void __launch_bounds__(256, 2)
tgemm_k(const __nv_bfloat16* __restrict__ ah, const __nv_bfloat16* __restrict__ al,
        const __nv_bfloat16* __restrict__ wh, const __nv_bfloat16* __restrict__ wl,
        const float* __restrict__ bias, const float* __restrict__ res,
        float* __restrict__ outf,
        __nv_bfloat16* __restrict__ outh, __nv_bfloat16* __restrict__ outl)
{
    extern __shared__ __align__(1024) char smem[];
    const uint32_t sb = smem_u32(smem);
    const int tid  = threadIdx.x;
    const int wid  = tid >> 5;
    const int lane = tid & 31;
    const int wm   = wid & 1;
    const int wn   = wid >> 1;
    const int n0   = blockIdx.x * BN;
    const int m0   = blockIdx.y * BM;

    if (tid < BN) ((float*)smem)[tid] = bias[n0 + tid];

    const __nv_bfloat16* Ah = ah + (size_t)m0 * HDIM;
    const __nv_bfloat16* Al = al + (size_t)m0 * HDIM;
    const __nv_bfloat16* Wh = wh + (size_t)n0 * HDIM;
    const __nv_bfloat16* Wl = wl + (size_t)n0 * HDIM;

    const int ldr = tid >> 1;              // row 0..127
    const int lds = tid & 1;               // 32B half of the 64B segment
    auto load_chunk = [&](int ch, int st) {
        const uint32_t so = sb + SM_ST + st*STAGE_B;
        const int cofs = ch * BK;
        const size_t g = (size_t)ldr*HDIM + cofs + lds*16;
        const uint32_t xa = ldr*128 + lds*32;
        CP16(so + swz(xa),               Ah + g);
        CP16(so + swz(xa + 16),          Ah + g + 8);
        CP16(so + swz(xa + 64),          Al + g);
        CP16(so + swz(xa + 80),          Al + g + 8);
        CP16(so + 16384 + swz(xa),       Wh + g);
        CP16(so + 16384 + swz(xa + 16),  Wh + g + 8);
        CP16(so + 16384 + swz(xa + 64),  Wl + g);
        CP16(so + 16384 + swz(xa + 80),  Wl + g + 8);
        CP_COMMIT();
    };

    float acc[4][4][4];
    #pragma unroll
    for (int i = 0; i < 4; ++i)
        #pragma unroll
        for (int j = 0; j < 4; ++j)
            #pragma unroll
            for (int r = 0; r < 4; ++r) acc[i][j][r] = 0.0f;

    load_chunk(0, 0);

    const int lr16 = lane & 15, lk = lane >> 4;
    const int NCH = HDIM / BK;             // 16
    for (int ch = 0; ch < NCH; ++ch) {
        if (ch < NCH-1) { load_chunk(ch + 1, (ch + 1) & 1); CP_WAIT(1); }
        else            { CP_WAIT(0); }
        __syncthreads();
        const uint32_t so = sb + SM_ST + (ch & 1)*STAGE_B;
        #pragma unroll
        for (int kk = 0; kk < 2; ++kk) {
            const uint32_t ka = kk*32 + lk*16;
            uint32_t fbh[2][4], fbl[2][4];
            #pragma unroll
            for (int p = 0; p < 2; ++p) {
                uint32_t bd = so + 16384 + swz((wn*32 + p*16 + lr16)*128 + ka);
                LDSM_X4(fbh[p][0], fbh[p][1], fbh[p][2], fbh[p][3], bd);
                uint32_t bdl = so + 16384 + swz((wn*32 + p*16 + lr16)*128 + 64 + ka);
                LDSM_X4(fbl[p][0], fbl[p][1], fbl[p][2], fbl[p][3], bdl);
            }
            #pragma unroll
            for (int mi = 0; mi < 4; ++mi) {
                uint32_t fah[4], fal[4];
                uint32_t ad = so + swz((wm*64 + mi*16 + lr16)*128 + ka);
                LDSM_X4(fah[0], fah[1], fah[2], fah[3], ad);
                uint32_t adl = so + swz((wm*64 + mi*16 + lr16)*128 + 64 + ka);
                LDSM_X4(fal[0], fal[1], fal[2], fal[3], adl);
                #pragma unroll
                for (int nj = 0; nj < 4; ++nj) {
                    const int p = nj >> 1, j = nj & 1;
                    MMA16816(acc[mi][nj], fah[0], fah[1], fah[2], fah[3],
                             fbh[p][j], fbh[p][j+2]);
                    MMA16816(acc[mi][nj], fah[0], fah[1], fah[2], fah[3],
                             fbl[p][j], fbl[p][j+2]);
                    MMA16816(acc[mi][nj], fal[0], fal[1], fal[2], fal[3],
                             fbh[p][j], fbh[p][j+2]);
                }
            }
        }
        __syncthreads();
    }

    // ---------------- epilogue ----------------
    const float* bsm = (const float*)smem;
    const int rbase = m0 + wm*64;
    const int clb   = wn*32;
    #pragma unroll
    for (int mi = 0; mi < 4; ++mi) {
        #pragma unroll
        for (int nj = 0; nj < 4; ++nj) {
            const int ca = clb + nj*8 + (lane & 3)*2;
            const float b0 = bsm[ca], b1 = bsm[ca + 1];
            #pragma unroll
            for (int hrow = 0; hrow < 2; ++hrow) {
                const int r = rbase + mi*16 + (lane >> 2) + hrow*8;
                float v0 = acc[mi][nj][hrow*2 + 0] + b0;
                float v1 = acc[mi][nj][hrow*2 + 1] + b1;
                const size_t off = (size_t)r * HDIM + n0 + ca;
                if (EPI == 1) {
                    float2 rr = *(const float2*)(res + off);
                    v0 += rr.x; v1 += rr.y;
                }
                if (EPI == 2) { v0 = gelu_f(v0); v1 = gelu_f(v1); }
                if (WF32) *(float2*)(outf + off) = make_float2(v0, v1);
                if (WHL) {
                    __nv_bfloat16 h0, l0, h1, l1;
                    split_bf(v0, h0, l0); split_bf(v1, h1, l1);
                    __nv_bfloat162 hh, ll;
                    hh.x = h0; hh.y = h1; ll.x = l0; ll.y = l1;
                    *(uint32_t*)(outh + off) = *(uint32_t*)&hh;
                    *(uint32_t*)(outl + off) = *(uint32_t*)&ll;
                }
            }
        }
    }
}

// ---------------- orchestration --------------------------------------------------
extern "C" void kernel_launch(void* const* d_in, const int* in_sizes, int n_in,
                              void* d_out, int out_size)
{
    const float* x      = (const float*)d_in[0];
    const float* ln1w   = (const float*)d_in[1];
    const float* ln1b   = (const float*)d_in[2];
    const float* ln2w   = (const float*)d_in[3];
    const float* ln2b   = (const float*)d_in[4];
    const float* log_dt = (const float*)d_in[5];
    const float* A_re   = (const float*)d_in[6];
    const float* A_im   = (const float*)d_in[7];
    const float* B_re   = (const float*)d_in[8];
    const float* B_im   = (const float*)d_in[9];
    const float* C_re   = (const float*)d_in[10];
    const float* C_im   = (const float*)d_in[11];
    const float* Dv     = (const float*)d_in[12];
    const float* Wk     = (const float*)d_in[13];
    const float* bk     = (const float*)d_in[14];
    const float* W1     = (const float*)d_in[15];
    const float* b1     = (const float*)d_in[16];
    const float* W2     = (const float*)d_in[17];
    const float* b2     = (const float*)d_in[18];
    const float* Wout   = (const float*)d_in[19];
    const float* bout   = (const float*)d_in[20];
    const float* Wproj  = (const float*)d_in[21];
    const float* bproj  = (const float*)d_in[22];

    cudaFuncSetAttribute(tgemm_k<0,false,true >, cudaFuncAttributeMaxDynamicSharedMemorySize, GEMM_SMEM);
    cudaFuncSetAttribute(tgemm_k<1,true ,true >, cudaFuncAttributeMaxDynamicSharedMemorySize, GEMM_SMEM);
    cudaFuncSetAttribute(tgemm_k<0,true ,false>, cudaFuncAttributeMaxDynamicSharedMemorySize, GEMM_SMEM);
    cudaFuncSetAttribute(tgemm_k<2,false,true >, cudaFuncAttributeMaxDynamicSharedMemorySize, GEMM_SMEM);
    cudaFuncSetAttribute(tgemm_k<1,true ,false>, cudaFuncAttributeMaxDynamicSharedMemorySize, GEMM_SMEM);

    float *fz, *fo1, *ftmp, *foutb;
    __nv_bfloat16 *p0h, *p0l, *p1h, *p1l, *wth, *wtl;
    cudaGetSymbolAddress((void**)&fz,   Fz);
    cudaGetSymbolAddress((void**)&fo1,  Fo1);
    cudaGetSymbolAddress((void**)&ftmp, Ftmp);
    cudaGetSymbolAddress((void**)&foutb,FoutB);
    cudaGetSymbolAddress((void**)&p0h,  P0h);
    cudaGetSymbolAddress((void**)&p0l,  P0l);
    cudaGetSymbolAddress((void**)&p1h,  P1h);
    cudaGetSymbolAddress((void**)&p1l,  P1l);
    cudaGetSymbolAddress((void**)&wth,  WTh);
    cudaGetSymbolAddress((void**)&wtl,  WTl);

    prec_k<<<(LYRS*HDIM*NHEAD + 255)/256, 256>>>(log_dt, A_re, A_im, B_re, B_im, C_re, C_im);
    wconv_k<<<dim3(16,16,10), dim3(32,8)>>>(Wk, W1, Wproj, W2, Wout);

    const dim3 gg(HDIM/BN, MROWS/BM);       // (4, 256)
    const dim3 tg(SEQ/32, HDIM/32, BATCH);
    const size_t WB = (size_t)HDIM*HDIM;
    const float* prev = x;
    for (int l = 0; l < LYRS; ++l) {
        int vo = l * HDIM;
        const __nv_bfloat16 *wkh = wth + (l*5+0)*WB, *wkl = wtl + (l*5+0)*WB;
        const __nv_bfloat16 *w1h = wth + (l*5+1)*WB, *w1l = wtl + (l*5+1)*WB;
        const __nv_bfloat16 *wph = wth + (l*5+2)*WB, *wpl = wtl + (l*5+2)*WB;
        const __nv_bfloat16 *w2h = wth + (l*5+3)*WB, *w2l = wtl + (l*5+3)*WB;
        const __nv_bfloat16 *woh = wth + (l*5+4)*WB, *wol = wtl + (l*5+4)*WB;

        ln_k<0><<<MROWS, 128>>>(prev, ln1w + vo, ln1b + vo, fz, nullptr, nullptr);
        tr_k<<<tg, dim3(32,8)>>>(fz, ftmp);
        scan_k<<<512, 256>>>(ftmp, p0h, p0l, Dv + vo, l);
        tgemm_k<0,false,true ><<<gg, 256, GEMM_SMEM>>>(p0h, p0l, wkh, wkl,
            bk + vo, nullptr, nullptr, p1h, p1l);
        tgemm_k<1,true ,true ><<<gg, 256, GEMM_SMEM>>>(p1h, p1l, w1h, w1l,
            b1 + vo, prev, fo1, p0h, p0l);
        ln_k<1><<<MROWS, 128>>>(fo1, ln2w + vo, ln2b + vo, nullptr, p1h, p1l);
        tgemm_k<0,true ,false><<<gg, 256, GEMM_SMEM>>>(p0h, p0l, wph, wpl,
            bproj + vo, nullptr, ftmp, nullptr, nullptr);
        tgemm_k<2,false,true ><<<gg, 256, GEMM_SMEM>>>(p1h, p1l, w2h, w2l,
            b2 + vo, nullptr, nullptr, p0h, p0l);
        float* op = (l == LYRS-1) ? (float*)d_out : foutb;
        tgemm_k<1,true ,false><<<gg, 256, GEMM_SMEM>>>(p0h, p0l, woh, wol,
            bout + vo, ftmp, op, nullptr, nullptr);
        prev = foutb;
    }
}

// round 10
// speedup vs baseline: 1.0881x; 1.0881x over previous
#include <cuda_runtime.h>
#include <cuda_bf16.h>
#include <math.h>
#include <stdint.h>

#define LYRS   2
#define HDIM   512
#define NHEAD  32
#define BATCH  8
#define SEQ    4096
#define MROWS  (BATCH*SEQ)
#define BLH    (MROWS*HDIM)

// GEMM tiling: CTA 128x128, 8 warps of 64x32, BK=64, 3-stage cp.async
#define BM 128
#define BN 128
#define BK 64
#define STAGE_B 65536                /* Ah16K + Al16K + Wh16K + Wl16K */
#define SM_ST   1024                 /* bias at 0..511 */
#define GEMM_SMEM (SM_ST + 3*STAGE_B)   /* 197632 */
#define LNTR_SMEM (512*33*4)            /* 67584 */

// ---------------- scratch ----------------------------------------------------
__device__ float Fo1[BLH], Ftmp[BLH], FoutB[BLH];
__device__ __nv_bfloat16 P0h[BLH], P0l[BLH], P1h[BLH], P1l[BLH];
__device__ __nv_bfloat16 WTh[10*HDIM*HDIM], WTl[10*HDIM*HDIM];
__device__ float g_lam_re[LYRS*HDIM*NHEAD], g_lam_im[LYRS*HDIM*NHEAD];
__device__ float g_co_re [LYRS*HDIM*NHEAD], g_co_im [LYRS*HDIM*NHEAD];

// ---------------- PTX helpers --------------------------------------------------
__device__ __forceinline__ uint32_t smem_u32(const void* p) {
    uint32_t a;
    asm("{ .reg .u64 t; cvta.to.shared.u64 t, %1; cvt.u32.u64 %0, t; }"
        : "=r"(a) : "l"(p));
    return a;
}
#define CP16(dst, src) \
    asm volatile("cp.async.cg.shared.global [%0], [%1], 16;" \
        :: "r"(dst), "l"(src) : "memory")
#define CP_COMMIT() asm volatile("cp.async.commit_group;" ::: "memory")
#define CP_WAIT(n)  asm volatile("cp.async.wait_group %0;" :: "n"(n) : "memory")

#define LDSM_X4(r0,r1,r2,r3, addr) \
    asm volatile("ldmatrix.sync.aligned.m8n8.x4.shared.b16 {%0,%1,%2,%3}, [%4];" \
        : "=r"(r0),"=r"(r1),"=r"(r2),"=r"(r3) : "r"(addr))

#define MMA16816(d, a0,a1,a2,a3, b0,b1) \
    asm volatile("mma.sync.aligned.m16n8k16.row.col.f32.bf16.bf16.f32 " \
        "{%0,%1,%2,%3}, {%4,%5,%6,%7}, {%8,%9}, {%0,%1,%2,%3};" \
        : "+f"((d)[0]),"+f"((d)[1]),"+f"((d)[2]),"+f"((d)[3]) \
        : "r"(a0),"r"(a1),"r"(a2),"r"(a3), "r"(b0),"r"(b1))

__device__ __forceinline__ uint32_t swz(uint32_t off) { return off ^ ((off >> 3) & 0x70); }
__device__ __forceinline__ float gelu_f(float x) {
    return 0.5f * x * (1.0f + erff(x * 0.70710678118654752440f));
}
__device__ __forceinline__ void split_bf(float v, __nv_bfloat16& h, __nv_bfloat16& l) {
    h = __float2bfloat16(v);
    l = __float2bfloat16(v - __bfloat162float(h));
}

// ---------------- SSM coefficient precompute ----------------------------------
__global__ void prec_k(const float* __restrict__ log_dt,
                       const float* __restrict__ A_re, const float* __restrict__ A_im,
                       const float* __restrict__ B_re, const float* __restrict__ B_im,
                       const float* __restrict__ C_re, const float* __restrict__ C_im)
{
    int idx = blockIdx.x * blockDim.x + threadIdx.x;
    if (idx >= LYRS*HDIM*NHEAD) return;
    int lh = idx / NHEAD;
    float dt = expf(log_dt[lh]);
    float ar = A_re[idx], ai = A_im[idx];
    float e = expf(dt*ar);
    float sn, cs; sincosf(dt*ai, &sn, &cs);
    float lr = e*cs, li = e*sn;
    float nr = lr - 1.0f, ni = li;
    float inv = 1.0f/(ar*ar + ai*ai);
    float dr = (nr*ar + ni*ai)*inv;
    float di = (ni*ar - nr*ai)*inv;
    float br = B_re[idx], bi = B_im[idx];
    float dbr = br*dr - bi*di;
    float dbi = br*di + bi*dr;
    float cr = C_re[idx], ci = C_im[idx];
    g_co_re[idx] = 2.0f*(cr*dbr - ci*dbi);
    g_co_im[idx] = 2.0f*(cr*dbi + ci*dbr);
    g_lam_re[idx] = lr;
    g_lam_im[idx] = li;
}

// ---------------- weight transpose + hi/lo split --------------------------------
__global__ void wconv_k(const float* __restrict__ Wk, const float* __restrict__ W1,
                        const float* __restrict__ Wproj, const float* __restrict__ W2,
                        const float* __restrict__ Wout)
{
    int widx = blockIdx.z;
    int l = widx / 5, t = widx % 5;
    const float* src = (t==0 ? Wk : t==1 ? W1 : t==2 ? Wproj : t==3 ? W2 : Wout)
                       + (size_t)l * HDIM * HDIM;
    __shared__ float tile[32][33];
    int tx = threadIdx.x, ty = threadIdx.y;
    int n0 = blockIdx.x*32, k0 = blockIdx.y*32;
    #pragma unroll
    for (int i = 0; i < 4; ++i)
        tile[ty + 8*i][tx] = src[(size_t)(k0 + ty + 8*i)*HDIM + n0 + tx];
    __syncthreads();
    #pragma unroll
    for (int i = 0; i < 4; ++i) {
        float v = tile[tx][ty + 8*i];
        size_t o = (size_t)widx*HDIM*HDIM + (size_t)(n0 + ty + 8*i)*HDIM + k0 + tx;
        __nv_bfloat16 h, lo; split_bf(v, h, lo);
        WTh[o] = h; WTl[o] = lo;
    }
}

// ---------------- fused LN1 + transpose: [B,L,H] fp32 -> LN -> [B,H,L] fp32 ----
// tile stored transposed [512h][33t]; all smem accesses scalar, conflict-free.
__global__ void __launch_bounds__(256)
ln_tr_k(const float* __restrict__ src, const float* __restrict__ g,
        const float* __restrict__ b, float* __restrict__ dst)
{
    extern __shared__ float tile[];          // [512][33]
    __shared__ float mu_s[32], rs_s[32];
    const int tid = threadIdx.x;
    const int t0  = blockIdx.x * 32;
    const int bb  = blockIdx.y;
    const int wid = tid >> 5, lane = tid & 31;

    // load 32 rows x 512 cols (coalesced float4), scatter transposed
    const float* sp = src + ((size_t)bb*SEQ + t0)*HDIM;
    const int r = tid >> 3, c8 = tid & 7;
    #pragma unroll
    for (int j = 0; j < 16; ++j) {
        int c4 = c8 + 8*j;
        float4 v = *(const float4*)(sp + (size_t)r*HDIM + c4*4);
        tile[(c4*4+0)*33 + r] = v.x;
        tile[(c4*4+1)*33 + r] = v.y;
        tile[(c4*4+2)*33 + r] = v.z;
        tile[(c4*4+3)*33 + r] = v.w;
    }
    __syncthreads();

    // per-row LN stats: warp w handles rows 4w..4w+3 (row = t index)
    #pragma unroll
    for (int rr = wid*4; rr < wid*4 + 4; ++rr) {
        float s = 0.f, q = 0.f;
        #pragma unroll
        for (int j = 0; j < 16; ++j) {
            float v = tile[(lane + 32*j)*33 + rr];
            s += v; q += v*v;
        }
        #pragma unroll
        for (int o = 16; o; o >>= 1) {
            s += __shfl_xor_sync(0xffffffffu, s, o);
            q += __shfl_xor_sync(0xffffffffu, q, o);
        }
        if (lane == 0) {
            float mu = s * (1.0f/HDIM);
            mu_s[rr] = mu;
            rs_s[rr] = rsqrtf(q*(1.0f/HDIM) - mu*mu + 1e-5f);
        }
    }
    __syncthreads();

    // transposed write with LN applied: dst[b][h][t0 + tq*4 .. +3]
    float* dp = dst + (size_t)bb*HDIM*SEQ + t0;
    const int tq = tid & 7;
    #pragma unroll
    for (int j = 0; j < 16; ++j) {
        int h = (tid >> 3) + 32*j;
        float gv = __ldg(g + h), bv = __ldg(b + h);
        float4 o;
        o.x = (tile[h*33 + tq*4+0] - mu_s[tq*4+0])*rs_s[tq*4+0]*gv + bv;
        o.y = (tile[h*33 + tq*4+1] - mu_s[tq*4+1])*rs_s[tq*4+1]*gv + bv;
        o.z = (tile[h*33 + tq*4+2] - mu_s[tq*4+2])*rs_s[tq*4+2]*gv + bv;
        o.w = (tile[h*33 + tq*4+3] - mu_s[tq*4+3])*rs_s[tq*4+3]*gv + bv;
        *(float4*)(dp + (size_t)h*SEQ + tq*4) = o;
    }
}

// ---------------- LayerNorm: fp32 in -> bf16 hi/lo out --------------------------
__global__ void __launch_bounds__(128)
ln_k(const float* __restrict__ src, const float* __restrict__ g,
     const float* __restrict__ b,
     __nv_bfloat16* __restrict__ dsth, __nv_bfloat16* __restrict__ dstl)
{
    const int m = blockIdx.x, tid = threadIdx.x;
    const float4 v = *(const float4*)(src + (size_t)m*HDIM + tid*4);
    float s = v.x + v.y + v.z + v.w;
    float q = v.x*v.x + v.y*v.y + v.z*v.z + v.w*v.w;
    #pragma unroll
    for (int o = 16; o; o >>= 1) {
        s += __shfl_xor_sync(0xffffffffu, s, o);
        q += __shfl_xor_sync(0xffffffffu, q, o);
    }
    __shared__ float ss[4], qq[4], mu_s, rs_s;
    int w = tid >> 5;
    if ((tid & 31) == 0) { ss[w] = s; qq[w] = q; }
    __syncthreads();
    if (tid == 0) {
        float S = ss[0]+ss[1]+ss[2]+ss[3];
        float Q = qq[0]+qq[1]+qq[2]+qq[3];
        float mu = S*(1.0f/HDIM);
        mu_s = mu; rs_s = rsqrtf(Q*(1.0f/HDIM) - mu*mu + 1e-5f);
    }
    __syncthreads();
    const float mu = mu_s, rs = rs_s;
    const float4 gv = *(const float4*)(g + tid*4);
    const float4 bv = *(const float4*)(b + tid*4);
    float4 o;
    o.x = (v.x - mu)*rs*gv.x + bv.x;
    o.y = (v.y - mu)*rs*gv.y + bv.y;
    o.z = (v.z - mu)*rs*gv.z + bv.z;
    o.w = (v.w - mu)*rs*gv.w + bv.w;
    size_t off = (size_t)m*HDIM + tid*4;
    __nv_bfloat16 h0,h1,h2,h3,l0,l1,l2,l3;
    split_bf(o.x,h0,l0); split_bf(o.y,h1,l1);
    split_bf(o.z,h2,l2); split_bf(o.w,h3,l3);
    __nv_bfloat162 a0, a1, c0, c1;
    a0.x=h0; a0.y=h1; a1.x=h2; a1.y=h3;
    c0.x=l0; c0.y=l1; c1.x=l2; c1.y=l3;
    *(uint2*)(dsth + off) = make_uint2(*(uint32_t*)&a0, *(uint32_t*)&a1);
    *(uint2*)(dstl + off) = make_uint2(*(uint32_t*)&c0, *(uint32_t*)&c1);
}

// ---------------- S4 scan + D-skip + GELU (R6 version) --------------------------
__global__ void __launch_bounds__(256)
scan_k(const float* __restrict__ zt, __nv_bfloat16* __restrict__ yh,
       __nv_bfloat16* __restrict__ yl, const float* __restrict__ Dvec, int l)
{
    __shared__ float st_s[8][32*36];
    __shared__ float zst[8][32];
    __shared__ float yt[2][32][9];
    const int tid  = threadIdx.x;
    const int wid  = tid >> 5;
    const int lane = tid & 31;
    const int b    = blockIdx.x >> 6;
    const int hg   = blockIdx.x & 63;
    const int h    = hg*8 + wid;
    const int base = l*HDIM*NHEAD + h*NHEAD + lane;
    const float lr = g_lam_re[base], li = g_lam_im[base];
    const float cr = g_co_re[base],  ci = g_co_im[base];
    const float nci = -ci;
    const float dsk = Dvec[h];
    const float* zp = zt + ((size_t)b*HDIM + h)*SEQ;
    float* st = st_s[wid];
    float* zs = zst[wid];
    const int ot = tid >> 3, oh = tid & 7;
    float sr = 0.0f, si = 0.0f;

    for (int t0 = 0; t0 < SEQ; t0 += 32) {
        float zv = zp[t0 + lane];
        zs[lane] = zv;
        __syncwarp();
        #pragma unroll
        for (int tt = 0; tt < 32; ++tt) {
            float zv_t = zs[tt];
            float tmp  = fmaf(-li, si, zv_t);
            float nsi  = fmaf(li, sr, lr*si);
            sr = fmaf(lr, sr, tmp);
            si = nsi;
            st[tt*36 + lane] = fmaf(cr, sr, nci*si);
        }
        __syncwarp();
        float a0 = 0.f, a1 = 0.f, a2 = 0.f, a3 = 0.f;
        const float4* rp = (const float4*)&st[lane*36];
        #pragma unroll
        for (int i = 0; i < 8; ++i) {
            float4 v4 = rp[i];
            a0 += v4.x; a1 += v4.y; a2 += v4.z; a3 += v4.w;
        }
        const int buf = (t0 >> 5) & 1;
        yt[buf][lane][wid] = gelu_f((a0 + a1) + (a2 + a3) + dsk * zv);
        __syncthreads();
        float v = yt[buf][ot][oh];
        __nv_bfloat16 hh, ll; split_bf(v, hh, ll);
        size_t off = ((size_t)(b*SEQ + t0 + ot))*HDIM + hg*8 + oh;
        yh[off] = hh; yl[off] = ll;
    }
}

// ---------------- bf16x3 mma.sync GEMM: 3-stage, 1 sync/chunk -------------------
template<int EPI, bool WF32, bool WHL>
__global__ void __launch_bounds__(256, 1)
tgemm_k(const __nv_bfloat16* __restrict__ ah, const __nv_bfloat16* __restrict__ al,
        const __nv_bfloat16* __restrict__ wh, const __nv_bfloat16* __restrict__ wl,
        const float* __restrict__ bias, const float* __restrict__ res,
        float* __restrict__ outf,
        __nv_bfloat16* __restrict__ outh, __nv_bfloat16* __restrict__ outl)
{
    extern __shared__ __align__(1024) char smem[];
    const uint32_t sb = smem_u32(smem);
    const int tid  = threadIdx.x;
    const int wid  = tid >> 5;
    const int lane = tid & 31;
    const int wm   = wid & 1;
    const int wn   = wid >> 1;
    const int n0   = blockIdx.x * BN;
    const int m0   = blockIdx.y * BM;

    if (tid < BN) ((float*)smem)[tid] = bias[n0 + tid];

    const __nv_bfloat16* Ah = ah + (size_t)m0 * HDIM;
    const __nv_bfloat16* Al = al + (size_t)m0 * HDIM;
    const __nv_bfloat16* Wh = wh + (size_t)n0 * HDIM;
    const __nv_bfloat16* Wl = wl + (size_t)n0 * HDIM;

    const int ldr = tid >> 3, ldc = tid & 7;
    auto load_chunk = [&](int ch, int st) {
        const uint32_t so = sb + SM_ST + st*STAGE_B;
        const int cofs = ch * BK;
        #pragma unroll
        for (int t = 0; t < 4; ++t) {
            int r = ldr + t*32;
            uint32_t dst = so + swz(r*128 + ldc*16);
            size_t gsrc = (size_t)r*HDIM + cofs + ldc*8;
            CP16(dst,         Ah + gsrc);
            CP16(dst + 16384, Al + gsrc);
            CP16(dst + 32768, Wh + gsrc);
            CP16(dst + 49152, Wl + gsrc);
        }
        CP_COMMIT();
    };

    float acc[4][4][4];
    #pragma unroll
    for (int i = 0; i < 4; ++i)
        #pragma unroll
        for (int j = 0; j < 4; ++j)
            #pragma unroll
            for (int r = 0; r < 4; ++r) acc[i][j][r] = 0.0f;

    load_chunk(0, 0);
    load_chunk(1, 1);

    const int lr16 = lane & 15, lk = lane >> 4;
    for (int ch = 0; ch < 8; ++ch) {
        if (ch < 7) { CP_WAIT(1); } else { CP_WAIT(0); }
        __syncthreads();
        if (ch + 2 < 8) load_chunk(ch + 2, (ch + 2) % 3);
        const uint32_t so = sb + SM_ST + (ch % 3)*STAGE_B;
        #pragma unroll
        for (int kk = 0; kk < 4; ++kk) {
            const uint32_t ka = kk*32 + lk*16;
            uint32_t fah[4][4], fal[4][4];
            #pragma unroll
            for (int mi = 0; mi < 4; ++mi) {
                uint32_t ad = so + swz((wm*64 + mi*16 + lr16)*128 + ka);
                LDSM_X4(fah[mi][0], fah[mi][1], fah[mi][2], fah[mi][3], ad);
                LDSM_X4(fal[mi][0], fal[mi][1], fal[mi][2], fal[mi][3], ad + 16384);
            }
            uint32_t fbh[2][4], fbl[2][4];
            #pragma unroll
            for (int p = 0; p < 2; ++p) {
                uint32_t bd = so + 32768 + swz((wn*32 + p*16 + lr16)*128 + ka);
                LDSM_X4(fbh[p][0], fbh[p][1], fbh[p][2], fbh[p][3], bd);
                LDSM_X4(fbl[p][0], fbl[p][1], fbl[p][2], fbl[p][3], bd + 16384);
            }
            #pragma unroll
            for (int mi = 0; mi < 4; ++mi) {
                #pragma unroll
                for (int nj = 0; nj < 4; ++nj) {
                    const int p = nj >> 1, j = nj & 1;
                    MMA16816(acc[mi][nj], fah[mi][0], fah[mi][1], fah[mi][2], fah[mi][3],
                             fbh[p][j], fbh[p][j+2]);
                    MMA16816(acc[mi][nj], fah[mi][0], fah[mi][1], fah[mi][2], fah[mi][3],
                             fbl[p][j], fbl[p][j+2]);
                    MMA16816(acc[mi][nj], fal[mi][0], fal[mi][1], fal[mi][2], fal[mi][3],
                             fbh[p][j], fbh[p][j+2]);
                }
            }
        }
    }

    // ---------------- epilogue ----------------
    const float* bsm = (const float*)smem;
    const int rbase = m0 + wm*64;
    const int clb   = wn*32;
    #pragma unroll
    for (int mi = 0; mi < 4; ++mi) {
        #pragma unroll
        for (int nj = 0; nj < 4; ++nj) {
            const int ca = clb + nj*8 + (lane & 3)*2;
            const float b0 = bsm[ca], b1 = bsm[ca + 1];
            #pragma unroll
            for (int hrow = 0; hrow < 2; ++hrow) {
                const int r = rbase + mi*16 + (lane >> 2) + hrow*8;
                float v0 = acc[mi][nj][hrow*2 + 0] + b0;
                float v1 = acc[mi][nj][hrow*2 + 1] + b1;
                const size_t off = (size_t)r * HDIM + n0 + ca;
                if (EPI == 1) {
                    float2 rr = *(const float2*)(res + off);
                    v0 += rr.x; v1 += rr.y;
                }
                if (EPI == 2) { v0 = gelu_f(v0); v1 = gelu_f(v1); }
                if (WF32) *(float2*)(outf + off) = make_float2(v0, v1);
                if (WHL) {
                    __nv_bfloat16 h0, l0, h1, l1;
                    split_bf(v0, h0, l0); split_bf(v1, h1, l1);
                    __nv_bfloat162 hh, ll;
                    hh.x = h0; hh.y = h1; ll.x = l0; ll.y = l1;
                    *(uint32_t*)(outh + off) = *(uint32_t*)&hh;
                    *(uint32_t*)(outl + off) = *(uint32_t*)&ll;
                }
            }
        }
    }
}

// ---------------- orchestration --------------------------------------------------
extern "C" void kernel_launch(void* const* d_in, const int* in_sizes, int n_in,
                              void* d_out, int out_size)
{
    const float* x      = (const float*)d_in[0];
    const float* ln1w   = (const float*)d_in[1];
    const float* ln1b   = (const float*)d_in[2];
    const float* ln2w   = (const float*)d_in[3];
    const float* ln2b   = (const float*)d_in[4];
    const float* log_dt = (const float*)d_in[5];
    const float* A_re   = (const float*)d_in[6];
    const float* A_im   = (const float*)d_in[7];
    const float* B_re   = (const float*)d_in[8];
    const float* B_im   = (const float*)d_in[9];
    const float* C_re   = (const float*)d_in[10];
    const float* C_im   = (const float*)d_in[11];
    const float* Dv     = (const float*)d_in[12];
    const float* Wk     = (const float*)d_in[13];
    const float* bk     = (const float*)d_in[14];
    const float* W1     = (const float*)d_in[15];
    const float* b1     = (const float*)d_in[16];
    const float* W2     = (const float*)d_in[17];
    const float* b2     = (const float*)d_in[18];
    const float* Wout   = (const float*)d_in[19];
    const float* bout   = (const float*)d_in[20];
    const float* Wproj  = (const float*)d_in[21];
    const float* bproj  = (const float*)d_in[22];

    cudaFuncSetAttribute(tgemm_k<0,false,true >, cudaFuncAttributeMaxDynamicSharedMemorySize, GEMM_SMEM);
    cudaFuncSetAttribute(tgemm_k<1,true ,true >, cudaFuncAttributeMaxDynamicSharedMemorySize, GEMM_SMEM);
    cudaFuncSetAttribute(tgemm_k<0,true ,false>, cudaFuncAttributeMaxDynamicSharedMemorySize, GEMM_SMEM);
    cudaFuncSetAttribute(tgemm_k<2,false,true >, cudaFuncAttributeMaxDynamicSharedMemorySize, GEMM_SMEM);
    cudaFuncSetAttribute(tgemm_k<1,true ,false>, cudaFuncAttributeMaxDynamicSharedMemorySize, GEMM_SMEM);
    cudaFuncSetAttribute(ln_tr_k, cudaFuncAttributeMaxDynamicSharedMemorySize, LNTR_SMEM);

    float *fo1, *ftmp, *foutb;
    __nv_bfloat16 *p0h, *p0l, *p1h, *p1l, *wth, *wtl;
    cudaGetSymbolAddress((void**)&fo1,  Fo1);
    cudaGetSymbolAddress((void**)&ftmp, Ftmp);
    cudaGetSymbolAddress((void**)&foutb,FoutB);
    cudaGetSymbolAddress((void**)&p0h,  P0h);
    cudaGetSymbolAddress((void**)&p0l,  P0l);
    cudaGetSymbolAddress((void**)&p1h,  P1h);
    cudaGetSymbolAddress((void**)&p1l,  P1l);
    cudaGetSymbolAddress((void**)&wth,  WTh);
    cudaGetSymbolAddress((void**)&wtl,  WTl);

    prec_k<<<(LYRS*HDIM*NHEAD + 255)/256, 256>>>(log_dt, A_re, A_im, B_re, B_im, C_re, C_im);
    wconv_k<<<dim3(16,16,10), dim3(32,8)>>>(Wk, W1, Wproj, W2, Wout);

    const dim3 gg(HDIM/BN, MROWS/BM);       // (4, 256)
    const size_t WB = (size_t)HDIM*HDIM;
    const float* prev = x;
    for (int l = 0; l < LYRS; ++l) {
        int vo = l * HDIM;
        const __nv_bfloat16 *wkh = wth + (l*5+0)*WB, *wkl = wtl + (l*5+0)*WB;
        const __nv_bfloat16 *w1h = wth + (l*5+1)*WB, *w1l = wtl + (l*5+1)*WB;
        const __nv_bfloat16 *wph = wth + (l*5+2)*WB, *wpl = wtl + (l*5+2)*WB;
        const __nv_bfloat16 *w2h = wth + (l*5+3)*WB, *w2l = wtl + (l*5+3)*WB;
        const __nv_bfloat16 *woh = wth + (l*5+4)*WB, *wol = wtl + (l*5+4)*WB;

        // zT = LN1(prev) transposed -> [B,H,L] fp32 (fused)
        ln_tr_k<<<dim3(SEQ/32, BATCH), 256, LNTR_SMEM>>>(prev, ln1w + vo, ln1b + vo, ftmp);
        // y = gelu(ssm(zT) + z*D) -> P0 hi/lo [B,L,H]
        scan_k<<<512, 256>>>(ftmp, p0h, p0l, Dv + vo, l);
        tgemm_k<0,false,true ><<<gg, 256, GEMM_SMEM>>>(p0h, p0l, wkh, wkl,
            bk + vo, nullptr, nullptr, p1h, p1l);
        tgemm_k<1,true ,true ><<<gg, 256, GEMM_SMEM>>>(p1h, p1l, w1h, w1l,
            b1 + vo, prev, fo1, p0h, p0l);
        ln_k<<<MROWS, 128>>>(fo1, ln2w + vo, ln2b + vo, p1h, p1l);
        tgemm_k<0,true ,false><<<gg, 256, GEMM_SMEM>>>(p0h, p0l, wph, wpl,
            bproj + vo, nullptr, ftmp, nullptr, nullptr);
        tgemm_k<2,false,true ><<<gg, 256, GEMM_SMEM>>>(p1h, p1l, w2h, w2l,
            b2 + vo, nullptr, nullptr, p0h, p0l);
        float* op = (l == LYRS-1) ? (float*)d_out : foutb;
        tgemm_k<1,true ,false><<<gg, 256, GEMM_SMEM>>>(p0h, p0l, woh, wol,
            bout + vo, ftmp, op, nullptr, nullptr);
        prev = foutb;
    }
}

// round 11
// speedup vs baseline: 1.1120x; 1.0220x over previous
#include <cuda_runtime.h>
#include <cuda_bf16.h>
#include <math.h>
#include <stdint.h>

#define LYRS   2
#define HDIM   512
#define NHEAD  32
#define BATCH  8
#define SEQ    4096
#define MROWS  (BATCH*SEQ)
#define BLH    (MROWS*HDIM)

// GEMM tiling: CTA 128x128, 8 warps of 64x32, BK=64, 3-stage cp.async
#define BM 128
#define BN 128
#define BK 64
#define STAGE_B 65536
#define SM_ST   1024
#define GEMM_SMEM (SM_ST + 3*STAGE_B)   /* 197632 */
#define LNTR_SMEM (512*33*4)            /* 67584 */

// ---------------- scratch ----------------------------------------------------
__device__ float Fo1[BLH], Ftmp[BLH], FoutB[BLH];
__device__ __nv_bfloat16 P0h[BLH], P0l[BLH], P1h[BLH], P1l[BLH];
__device__ __nv_bfloat16 WTh[10*HDIM*HDIM], WTl[10*HDIM*HDIM];
__device__ float g_lam_re[LYRS*HDIM*NHEAD], g_lam_im[LYRS*HDIM*NHEAD];
__device__ float g_co_re [LYRS*HDIM*NHEAD], g_co_im [LYRS*HDIM*NHEAD];

// ---------------- PTX helpers --------------------------------------------------
__device__ __forceinline__ uint32_t smem_u32(const void* p) {
    uint32_t a;
    asm("{ .reg .u64 t; cvta.to.shared.u64 t, %1; cvt.u32.u64 %0, t; }"
        : "=r"(a) : "l"(p));
    return a;
}
#define CP16(dst, src) \
    asm volatile("cp.async.cg.shared.global [%0], [%1], 16;" \
        :: "r"(dst), "l"(src) : "memory")
#define CP_COMMIT() asm volatile("cp.async.commit_group;" ::: "memory")
#define CP_WAIT(n)  asm volatile("cp.async.wait_group %0;" :: "n"(n) : "memory")

#define LDSM_X4(r0,r1,r2,r3, addr) \
    asm volatile("ldmatrix.sync.aligned.m8n8.x4.shared.b16 {%0,%1,%2,%3}, [%4];" \
        : "=r"(r0),"=r"(r1),"=r"(r2),"=r"(r3) : "r"(addr))

#define MMA16816(d, a0,a1,a2,a3, b0,b1) \
    asm volatile("mma.sync.aligned.m16n8k16.row.col.f32.bf16.bf16.f32 " \
        "{%0,%1,%2,%3}, {%4,%5,%6,%7}, {%8,%9}, {%0,%1,%2,%3};" \
        : "+f"((d)[0]),"+f"((d)[1]),"+f"((d)[2]),"+f"((d)[3]) \
        : "r"(a0),"r"(a1),"r"(a2),"r"(a3), "r"(b0),"r"(b1))

__device__ __forceinline__ uint32_t swz(uint32_t off) { return off ^ ((off >> 3) & 0x70); }
__device__ __forceinline__ float gelu_f(float x) {
    return 0.5f * x * (1.0f + erff(x * 0.70710678118654752440f));
}
__device__ __forceinline__ void split_bf(float v, __nv_bfloat16& h, __nv_bfloat16& l) {
    h = __float2bfloat16(v);
    l = __float2bfloat16(v - __bfloat162float(h));
}

// ---------------- SSM coefficient precompute ----------------------------------
__global__ void prec_k(const float* __restrict__ log_dt,
                       const float* __restrict__ A_re, const float* __restrict__ A_im,
                       const float* __restrict__ B_re, const float* __restrict__ B_im,
                       const float* __restrict__ C_re, const float* __restrict__ C_im)
{
    int idx = blockIdx.x * blockDim.x + threadIdx.x;
    if (idx >= LYRS*HDIM*NHEAD) return;
    int lh = idx / NHEAD;
    float dt = expf(log_dt[lh]);
    float ar = A_re[idx], ai = A_im[idx];
    float e = expf(dt*ar);
    float sn, cs; sincosf(dt*ai, &sn, &cs);
    float lr = e*cs, li = e*sn;
    float nr = lr - 1.0f, ni = li;
    float inv = 1.0f/(ar*ar + ai*ai);
    float dr = (nr*ar + ni*ai)*inv;
    float di = (ni*ar - nr*ai)*inv;
    float br = B_re[idx], bi = B_im[idx];
    float dbr = br*dr - bi*di;
    float dbi = br*di + bi*dr;
    float cr = C_re[idx], ci = C_im[idx];
    g_co_re[idx] = 2.0f*(cr*dbr - ci*dbi);
    g_co_im[idx] = 2.0f*(cr*dbi + ci*dbr);
    g_lam_re[idx] = lr;
    g_lam_im[idx] = li;
}

// ---------------- weight transpose + hi/lo split --------------------------------
__global__ void wconv_k(const float* __restrict__ Wk, const float* __restrict__ W1,
                        const float* __restrict__ Wproj, const float* __restrict__ W2,
                        const float* __restrict__ Wout)
{
    int widx = blockIdx.z;
    int l = widx / 5, t = widx % 5;
    const float* src = (t==0 ? Wk : t==1 ? W1 : t==2 ? Wproj : t==3 ? W2 : Wout)
                       + (size_t)l * HDIM * HDIM;
    __shared__ float tile[32][33];
    int tx = threadIdx.x, ty = threadIdx.y;
    int n0 = blockIdx.x*32, k0 = blockIdx.y*32;
    #pragma unroll
    for (int i = 0; i < 4; ++i)
        tile[ty + 8*i][tx] = src[(size_t)(k0 + ty + 8*i)*HDIM + n0 + tx];
    __syncthreads();
    #pragma unroll
    for (int i = 0; i < 4; ++i) {
        float v = tile[tx][ty + 8*i];
        size_t o = (size_t)widx*HDIM*HDIM + (size_t)(n0 + ty + 8*i)*HDIM + k0 + tx;
        __nv_bfloat16 h, lo; split_bf(v, h, lo);
        WTh[o] = h; WTl[o] = lo;
    }
}

// ---------------- fused LN1 + transpose: [B,L,H] fp32 -> LN -> [B,H,L] fp32 ----
__global__ void __launch_bounds__(256)
ln_tr_k(const float* __restrict__ src, const float* __restrict__ g,
        const float* __restrict__ b, float* __restrict__ dst)
{
    extern __shared__ float tile[];          // [512][33]
    __shared__ float mu_s[32], rs_s[32];
    const int tid = threadIdx.x;
    const int t0  = blockIdx.x * 32;
    const int bb  = blockIdx.y;
    const int wid = tid >> 5, lane = tid & 31;

    const float* sp = src + ((size_t)bb*SEQ + t0)*HDIM;
    const int r = tid >> 3, c8 = tid & 7;
    #pragma unroll
    for (int j = 0; j < 16; ++j) {
        int c4 = c8 + 8*j;
        float4 v = *(const float4*)(sp + (size_t)r*HDIM + c4*4);
        tile[(c4*4+0)*33 + r] = v.x;
        tile[(c4*4+1)*33 + r] = v.y;
        tile[(c4*4+2)*33 + r] = v.z;
        tile[(c4*4+3)*33 + r] = v.w;
    }
    __syncthreads();

    #pragma unroll
    for (int rr = wid*4; rr < wid*4 + 4; ++rr) {
        float s = 0.f, q = 0.f;
        #pragma unroll
        for (int j = 0; j < 16; ++j) {
            float v = tile[(lane + 32*j)*33 + rr];
            s += v; q += v*v;
        }
        #pragma unroll
        for (int o = 16; o; o >>= 1) {
            s += __shfl_xor_sync(0xffffffffu, s, o);
            q += __shfl_xor_sync(0xffffffffu, q, o);
        }
        if (lane == 0) {
            float mu = s * (1.0f/HDIM);
            mu_s[rr] = mu;
            rs_s[rr] = rsqrtf(q*(1.0f/HDIM) - mu*mu + 1e-5f);
        }
    }
    __syncthreads();

    float* dp = dst + (size_t)bb*HDIM*SEQ + t0;
    const int tq = tid & 7;
    #pragma unroll
    for (int j = 0; j < 16; ++j) {
        int h = (tid >> 3) + 32*j;
        float gv = __ldg(g + h), bv = __ldg(b + h);
        float4 o;
        o.x = (tile[h*33 + tq*4+0] - mu_s[tq*4+0])*rs_s[tq*4+0]*gv + bv;
        o.y = (tile[h*33 + tq*4+1] - mu_s[tq*4+1])*rs_s[tq*4+1]*gv + bv;
        o.z = (tile[h*33 + tq*4+2] - mu_s[tq*4+2])*rs_s[tq*4+2]*gv + bv;
        o.w = (tile[h*33 + tq*4+3] - mu_s[tq*4+3])*rs_s[tq*4+3]*gv + bv;
        *(float4*)(dp + (size_t)h*SEQ + tq*4) = o;
    }
}

// ---------------- LayerNorm: fp32 in -> bf16 hi/lo out --------------------------
__global__ void __launch_bounds__(128)
ln_k(const float* __restrict__ src, const float* __restrict__ g,
     const float* __restrict__ b,
     __nv_bfloat16* __restrict__ dsth, __nv_bfloat16* __restrict__ dstl)
{
    const int m = blockIdx.x, tid = threadIdx.x;
    const float4 v = *(const float4*)(src + (size_t)m*HDIM + tid*4);
    float s = v.x + v.y + v.z + v.w;
    float q = v.x*v.x + v.y*v.y + v.z*v.z + v.w*v.w;
    #pragma unroll
    for (int o = 16; o; o >>= 1) {
        s += __shfl_xor_sync(0xffffffffu, s, o);
        q += __shfl_xor_sync(0xffffffffu, q, o);
    }
    __shared__ float ss[4], qq[4], mu_s, rs_s;
    int w = tid >> 5;
    if ((tid & 31) == 0) { ss[w] = s; qq[w] = q; }
    __syncthreads();
    if (tid == 0) {
        float S = ss[0]+ss[1]+ss[2]+ss[3];
        float Q = qq[0]+qq[1]+qq[2]+qq[3];
        float mu = S*(1.0f/HDIM);
        mu_s = mu; rs_s = rsqrtf(Q*(1.0f/HDIM) - mu*mu + 1e-5f);
    }
    __syncthreads();
    const float mu = mu_s, rs = rs_s;
    const float4 gv = *(const float4*)(g + tid*4);
    const float4 bv = *(const float4*)(b + tid*4);
    float4 o;
    o.x = (v.x - mu)*rs*gv.x + bv.x;
    o.y = (v.y - mu)*rs*gv.y + bv.y;
    o.z = (v.z - mu)*rs*gv.z + bv.z;
    o.w = (v.w - mu)*rs*gv.w + bv.w;
    size_t off = (size_t)m*HDIM + tid*4;
    __nv_bfloat16 h0,h1,h2,h3,l0,l1,l2,l3;
    split_bf(o.x,h0,l0); split_bf(o.y,h1,l1);
    split_bf(o.z,h2,l2); split_bf(o.w,h3,l3);
    __nv_bfloat162 a0, a1, c0, c1;
    a0.x=h0; a0.y=h1; a1.x=h2; a1.y=h3;
    c0.x=l0; c0.y=l1; c1.x=l2; c1.y=l3;
    *(uint2*)(dsth + off) = make_uint2(*(uint32_t*)&a0, *(uint32_t*)&a1);
    *(uint2*)(dstl + off) = make_uint2(*(uint32_t*)&c0, *(uint32_t*)&c1);
}

// ---------------- S4 scan + D-skip + GELU: 4 warps/block, z prefetch ------------
// grid 1024 (b x 128 h-groups of 4); ~10 blocks/SM resident.
__global__ void __launch_bounds__(128)
scan_k(const float* __restrict__ zt, __nv_bfloat16* __restrict__ yh,
       __nv_bfloat16* __restrict__ yl, const float* __restrict__ Dvec, int l)
{
    __shared__ float st_s[4][32*36];
    __shared__ float zst[4][32];
    __shared__ float yt[2][32][9];
    const int tid  = threadIdx.x;
    const int wid  = tid >> 5;
    const int lane = tid & 31;
    const int b    = blockIdx.x >> 7;
    const int hg   = blockIdx.x & 127;           // group of 4 h
    const int h    = hg*4 + wid;
    const int base = l*HDIM*NHEAD + h*NHEAD + lane;
    const float lr = g_lam_re[base], li = g_lam_im[base];
    const float cr = g_co_re[base],  ci = g_co_im[base];
    const float nci = -ci;
    const float dsk = Dvec[h];
    const float* zp = zt + ((size_t)b*HDIM + h)*SEQ;
    float* st = st_s[wid];
    float* zs = zst[wid];
    const int ot = tid >> 2, oh = tid & 3;
    float sr = 0.0f, si = 0.0f;

    float zv = zp[lane];                          // prefetch era 0
    for (int t0 = 0; t0 < SEQ; t0 += 32) {
        float zv_next = (t0 + 32 < SEQ) ? zp[t0 + 32 + lane] : 0.0f;
        zs[lane] = zv;
        __syncwarp();
        #pragma unroll
        for (int tt = 0; tt < 32; ++tt) {
            float zv_t = zs[tt];
            float tmp  = fmaf(-li, si, zv_t);
            float nsi  = fmaf(li, sr, lr*si);
            sr = fmaf(lr, sr, tmp);
            si = nsi;
            st[tt*36 + lane] = fmaf(cr, sr, nci*si);
        }
        __syncwarp();
        float a0 = 0.f, a1 = 0.f, a2 = 0.f, a3 = 0.f;
        const float4* rp = (const float4*)&st[lane*36];
        #pragma unroll
        for (int i = 0; i < 8; ++i) {
            float4 v4 = rp[i];
            a0 += v4.x; a1 += v4.y; a2 += v4.z; a3 += v4.w;
        }
        const int buf = (t0 >> 5) & 1;
        yt[buf][lane][wid] = gelu_f((a0 + a1) + (a2 + a3) + dsk * zv);
        __syncthreads();
        float v = yt[buf][ot][oh];
        __nv_bfloat16 hh, ll; split_bf(v, hh, ll);
        size_t off = ((size_t)(b*SEQ + t0 + ot))*HDIM + hg*4 + oh;
        yh[off] = hh; yl[off] = ll;
        zv = zv_next;
    }
}

// ---------------- bf16x3 mma.sync GEMM: 3-stage, 1 sync/chunk -------------------
template<int EPI, bool WF32, bool WHL>
__global__ void __launch_bounds__(256, 1)
tgemm_k(const __nv_bfloat16* __restrict__ ah, const __nv_bfloat16* __restrict__ al,
        const __nv_bfloat16* __restrict__ wh, const __nv_bfloat16* __restrict__ wl,
        const float* __restrict__ bias, const float* __restrict__ res,
        float* __restrict__ outf,
        __nv_bfloat16* __restrict__ outh, __nv_bfloat16* __restrict__ outl)
{
    extern __shared__ __align__(1024) char smem[];
    const uint32_t sb = smem_u32(smem);
    const int tid  = threadIdx.x;
    const int wid  = tid >> 5;
    const int lane = tid & 31;
    const int wm   = wid & 1;
    const int wn   = wid >> 1;
    const int n0   = blockIdx.x * BN;
    const int m0   = blockIdx.y * BM;

    if (tid < BN) ((float*)smem)[tid] = bias[n0 + tid];

    const __nv_bfloat16* Ah = ah + (size_t)m0 * HDIM;
    const __nv_bfloat16* Al = al + (size_t)m0 * HDIM;
    const __nv_bfloat16* Wh = wh + (size_t)n0 * HDIM;
    const __nv_bfloat16* Wl = wl + (size_t)n0 * HDIM;

    const int ldr = tid >> 3, ldc = tid & 7;
    auto load_chunk = [&](int ch, int st) {
        const uint32_t so = sb + SM_ST + st*STAGE_B;
        const int cofs = ch * BK;
        #pragma unroll
        for (int t = 0; t < 4; ++t) {
            int r = ldr + t*32;
            uint32_t dst = so + swz(r*128 + ldc*16);
            size_t gsrc = (size_t)r*HDIM + cofs + ldc*8;
            CP16(dst,         Ah + gsrc);
            CP16(dst + 16384, Al + gsrc);
            CP16(dst + 32768, Wh + gsrc);
            CP16(dst + 49152, Wl + gsrc);
        }
        CP_COMMIT();
    };

    float acc[4][4][4];
    #pragma unroll
    for (int i = 0; i < 4; ++i)
        #pragma unroll
        for (int j = 0; j < 4; ++j)
            #pragma unroll
            for (int r = 0; r < 4; ++r) acc[i][j][r] = 0.0f;

    load_chunk(0, 0);
    load_chunk(1, 1);

    const int lr16 = lane & 15, lk = lane >> 4;
    for (int ch = 0; ch < 8; ++ch) {
        if (ch < 7) { CP_WAIT(1); } else { CP_WAIT(0); }
        __syncthreads();
        if (ch + 2 < 8) load_chunk(ch + 2, (ch + 2) % 3);
        const uint32_t so = sb + SM_ST + (ch % 3)*STAGE_B;
        #pragma unroll
        for (int kk = 0; kk < 4; ++kk) {
            const uint32_t ka = kk*32 + lk*16;
            uint32_t fah[4][4], fal[4][4];
            #pragma unroll
            for (int mi = 0; mi < 4; ++mi) {
                uint32_t ad = so + swz((wm*64 + mi*16 + lr16)*128 + ka);
                LDSM_X4(fah[mi][0], fah[mi][1], fah[mi][2], fah[mi][3], ad);
                LDSM_X4(fal[mi][0], fal[mi][1], fal[mi][2], fal[mi][3], ad + 16384);
            }
            uint32_t fbh[2][4], fbl[2][4];
            #pragma unroll
            for (int p = 0; p < 2; ++p) {
                uint32_t bd = so + 32768 + swz((wn*32 + p*16 + lr16)*128 + ka);
                LDSM_X4(fbh[p][0], fbh[p][1], fbh[p][2], fbh[p][3], bd);
                LDSM_X4(fbl[p][0], fbl[p][1], fbl[p][2], fbl[p][3], bd + 16384);
            }
            #pragma unroll
            for (int mi = 0; mi < 4; ++mi) {
                #pragma unroll
                for (int nj = 0; nj < 4; ++nj) {
                    const int p = nj >> 1, j = nj & 1;
                    MMA16816(acc[mi][nj], fah[mi][0], fah[mi][1], fah[mi][2], fah[mi][3],
                             fbh[p][j], fbh[p][j+2]);
                    MMA16816(acc[mi][nj], fah[mi][0], fah[mi][1], fah[mi][2], fah[mi][3],
                             fbl[p][j], fbl[p][j+2]);
                    MMA16816(acc[mi][nj], fal[mi][0], fal[mi][1], fal[mi][2], fal[mi][3],
                             fbh[p][j], fbh[p][j+2]);
                }
            }
        }
    }

    // ---------------- epilogue ----------------
    const float* bsm = (const float*)smem;
    const int rbase = m0 + wm*64;
    const int clb   = wn*32;
    #pragma unroll
    for (int mi = 0; mi < 4; ++mi) {
        #pragma unroll
        for (int nj = 0; nj < 4; ++nj) {
            const int ca = clb + nj*8 + (lane & 3)*2;
            const float b0 = bsm[ca], b1 = bsm[ca + 1];
            #pragma unroll
            for (int hrow = 0; hrow < 2; ++hrow) {
                const int r = rbase + mi*16 + (lane >> 2) + hrow*8;
                float v0 = acc[mi][nj][hrow*2 + 0] + b0;
                float v1 = acc[mi][nj][hrow*2 + 1] + b1;
                const size_t off = (size_t)r * HDIM + n0 + ca;
                if (EPI == 1) {
                    float2 rr = *(const float2*)(res + off);
                    v0 += rr.x; v1 += rr.y;
                }
                if (EPI == 2) { v0 = gelu_f(v0); v1 = gelu_f(v1); }
                if (WF32) *(float2*)(outf + off) = make_float2(v0, v1);
                if (WHL) {
                    __nv_bfloat16 h0, l0, h1, l1;
                    split_bf(v0, h0, l0); split_bf(v1, h1, l1);
                    __nv_bfloat162 hh, ll;
                    hh.x = h0; hh.y = h1; ll.x = l0; ll.y = l1;
                    *(uint32_t*)(outh + off) = *(uint32_t*)&hh;
                    *(uint32_t*)(outl + off) = *(uint32_t*)&ll;
                }
            }
        }
    }
}

// ---------------- orchestration --------------------------------------------------
extern "C" void kernel_launch(void* const* d_in, const int* in_sizes, int n_in,
                              void* d_out, int out_size)
{
    const float* x      = (const float*)d_in[0];
    const float* ln1w   = (const float*)d_in[1];
    const float* ln1b   = (const float*)d_in[2];
    const float* ln2w   = (const float*)d_in[3];
    const float* ln2b   = (const float*)d_in[4];
    const float* log_dt = (const float*)d_in[5];
    const float* A_re   = (const float*)d_in[6];
    const float* A_im   = (const float*)d_in[7];
    const float* B_re   = (const float*)d_in[8];
    const float* B_im   = (const float*)d_in[9];
    const float* C_re   = (const float*)d_in[10];
    const float* C_im   = (const float*)d_in[11];
    const float* Dv     = (const float*)d_in[12];
    const float* Wk     = (const float*)d_in[13];
    const float* bk     = (const float*)d_in[14];
    const float* W1     = (const float*)d_in[15];
    const float* b1     = (const float*)d_in[16];
    const float* W2     = (const float*)d_in[17];
    const float* b2     = (const float*)d_in[18];
    const float* Wout   = (const float*)d_in[19];
    const float* bout   = (const float*)d_in[20];
    const float* Wproj  = (const float*)d_in[21];
    const float* bproj  = (const float*)d_in[22];

    cudaFuncSetAttribute(tgemm_k<0,false,true >, cudaFuncAttributeMaxDynamicSharedMemorySize, GEMM_SMEM);
    cudaFuncSetAttribute(tgemm_k<1,true ,true >, cudaFuncAttributeMaxDynamicSharedMemorySize, GEMM_SMEM);
    cudaFuncSetAttribute(tgemm_k<0,true ,false>, cudaFuncAttributeMaxDynamicSharedMemorySize, GEMM_SMEM);
    cudaFuncSetAttribute(tgemm_k<2,false,true >, cudaFuncAttributeMaxDynamicSharedMemorySize, GEMM_SMEM);
    cudaFuncSetAttribute(tgemm_k<1,true ,false>, cudaFuncAttributeMaxDynamicSharedMemorySize, GEMM_SMEM);
    cudaFuncSetAttribute(ln_tr_k, cudaFuncAttributeMaxDynamicSharedMemorySize, LNTR_SMEM);

    float *fo1, *ftmp, *foutb;
    __nv_bfloat16 *p0h, *p0l, *p1h, *p1l, *wth, *wtl;
    cudaGetSymbolAddress((void**)&fo1,  Fo1);
    cudaGetSymbolAddress((void**)&ftmp, Ftmp);
    cudaGetSymbolAddress((void**)&foutb,FoutB);
    cudaGetSymbolAddress((void**)&p0h,  P0h);
    cudaGetSymbolAddress((void**)&p0l,  P0l);
    cudaGetSymbolAddress((void**)&p1h,  P1h);
    cudaGetSymbolAddress((void**)&p1l,  P1l);
    cudaGetSymbolAddress((void**)&wth,  WTh);
    cudaGetSymbolAddress((void**)&wtl,  WTl);

    prec_k<<<(LYRS*HDIM*NHEAD + 255)/256, 256>>>(log_dt, A_re, A_im, B_re, B_im, C_re, C_im);
    wconv_k<<<dim3(16,16,10), dim3(32,8)>>>(Wk, W1, Wproj, W2, Wout);

    const dim3 gg(HDIM/BN, MROWS/BM);       // (4, 256)
    const size_t WB = (size_t)HDIM*HDIM;
    const float* prev = x;
    for (int l = 0; l < LYRS; ++l) {
        int vo = l * HDIM;
        const __nv_bfloat16 *wkh = wth + (l*5+0)*WB, *wkl = wtl + (l*5+0)*WB;
        const __nv_bfloat16 *w1h = wth + (l*5+1)*WB, *w1l = wtl + (l*5+1)*WB;
        const __nv_bfloat16 *wph = wth + (l*5+2)*WB, *wpl = wtl + (l*5+2)*WB;
        const __nv_bfloat16 *w2h = wth + (l*5+3)*WB, *w2l = wtl + (l*5+3)*WB;
        const __nv_bfloat16 *woh = wth + (l*5+4)*WB, *wol = wtl + (l*5+4)*WB;

        // zT = LN1(prev) transposed -> [B,H,L] fp32 (fused)
        ln_tr_k<<<dim3(SEQ/32, BATCH), 256, LNTR_SMEM>>>(prev, ln1w + vo, ln1b + vo, ftmp);
        // y = gelu(ssm(zT) + z*D) -> P0 hi/lo [B,L,H]
        scan_k<<<1024, 128>>>(ftmp, p0h, p0l, Dv + vo, l);
        tgemm_k<0,false,true ><<<gg, 256, GEMM_SMEM>>>(p0h, p0l, wkh, wkl,
            bk + vo, nullptr, nullptr, p1h, p1l);
        tgemm_k<1,true ,true ><<<gg, 256, GEMM_SMEM>>>(p1h, p1l, w1h, w1l,
            b1 + vo, prev, fo1, p0h, p0l);
        ln_k<<<MROWS, 128>>>(fo1, ln2w + vo, ln2b + vo, p1h, p1l);
        tgemm_k<0,true ,false><<<gg, 256, GEMM_SMEM>>>(p0h, p0l, wph, wpl,
            bproj + vo, nullptr, ftmp, nullptr, nullptr);
        tgemm_k<2,false,true ><<<gg, 256, GEMM_SMEM>>>(p1h, p1l, w2h, w2l,
            b2 + vo, nullptr, nullptr, p0h, p0l);
        float* op = (l == LYRS-1) ? (float*)d_out : foutb;
        tgemm_k<1,true ,false><<<gg, 256, GEMM_SMEM>>>(p0h, p0l, woh, wol,
            bout + vo, ftmp, op, nullptr, nullptr);
        prev = foutb;
    }
}